// round 1
// baseline (speedup 1.0000x reference)
#include <cuda_runtime.h>
#include <cuda_bf16.h>
#include <cstdint>

// Problem constants
#define BATCH 2
#define SEQ 2048
#define DIM 1024
#define NHEADS 16
#define HDIM 64
#define SM_SCALE 0.125f   // 1/sqrt(64)

// Scratch (device globals: allocation-free)
__device__ float g_qkv[(size_t)BATCH * SEQ * 3 * DIM];   // [B, L, 3*D]  (48 MB)
__device__ float g_attn[(size_t)BATCH * SEQ * DIM];      // [B, L, D]    (16 MB)

// ---------------------------------------------------------------------------
// SGEMM NT: C[M,N] = A[M,K] * B[N,K]^T   (both A and B are K-contiguous)
// 128x128 block tile, K-tile 8, 256 threads, 8x8 per-thread micro-tile.
// ---------------------------------------------------------------------------
__device__ __forceinline__ void sgemm_nt_body(
    const float* __restrict__ A, const float* __restrict__ B,
    float* __restrict__ C, int M, int N, int K)
{
    __shared__ float As[8][128];
    __shared__ float Bs[8][128];

    const int tid = threadIdx.x;
    const int bm = blockIdx.y * 128;
    const int bn = blockIdx.x * 128;

    // gmem load mapping: each thread loads one float4 of A and one of B per K-tile
    const int lr = tid >> 1;             // 0..127 (tile row)
    const int lk = (tid & 1) << 2;       // 0 or 4 (k offset)
    const float* Ag = A + (size_t)(bm + lr) * K + lk;
    const float* Bg = B + (size_t)(bn + lr) * K + lk;

    const int tx = tid & 15;             // col group
    const int ty = tid >> 4;             // row group

    float acc[8][8];
#pragma unroll
    for (int i = 0; i < 8; i++)
#pragma unroll
        for (int j = 0; j < 8; j++) acc[i][j] = 0.f;

    float4 a4 = *(const float4*)Ag;
    float4 b4 = *(const float4*)Bg;

    for (int kt = 0; kt < K; kt += 8) {
        // store current fragments to smem (transposed: [k][m])
        As[lk + 0][lr] = a4.x; As[lk + 1][lr] = a4.y;
        As[lk + 2][lr] = a4.z; As[lk + 3][lr] = a4.w;
        Bs[lk + 0][lr] = b4.x; Bs[lk + 1][lr] = b4.y;
        Bs[lk + 2][lr] = b4.z; Bs[lk + 3][lr] = b4.w;
        __syncthreads();

        // prefetch next K-tile
        if (kt + 8 < K) {
            a4 = *(const float4*)(Ag + kt + 8);
            b4 = *(const float4*)(Bg + kt + 8);
        }

#pragma unroll
        for (int k = 0; k < 8; k++) {
            float4 a0 = *(const float4*)&As[k][ty * 8];
            float4 a1 = *(const float4*)&As[k][ty * 8 + 4];
            float4 b0 = *(const float4*)&Bs[k][tx * 8];
            float4 b1 = *(const float4*)&Bs[k][tx * 8 + 4];
            float af[8] = {a0.x, a0.y, a0.z, a0.w, a1.x, a1.y, a1.z, a1.w};
            float bf[8] = {b0.x, b0.y, b0.z, b0.w, b1.x, b1.y, b1.z, b1.w};
#pragma unroll
            for (int i = 0; i < 8; i++)
#pragma unroll
                for (int j = 0; j < 8; j++)
                    acc[i][j] += af[i] * bf[j];
        }
        __syncthreads();
    }

#pragma unroll
    for (int i = 0; i < 8; i++) {
        float* Cr = C + (size_t)(bm + ty * 8 + i) * N + bn + tx * 8;
        *(float4*)(Cr)     = make_float4(acc[i][0], acc[i][1], acc[i][2], acc[i][3]);
        *(float4*)(Cr + 4) = make_float4(acc[i][4], acc[i][5], acc[i][6], acc[i][7]);
    }
}

__global__ __launch_bounds__(256, 2)
void gemm_qkv(const float* __restrict__ x, const float* __restrict__ w_qkv)
{
    // qkv[M=4096, N=3072] = x[4096,1024] @ w_qkv[3072,1024]^T
    sgemm_nt_body(x, w_qkv, g_qkv, BATCH * SEQ, 3 * DIM, DIM);
}

__global__ __launch_bounds__(256, 2)
void gemm_proj(const float* __restrict__ w_proj, float* __restrict__ out)
{
    // out[4096,1024] = attn_out[4096,1024] @ w_proj[1024,1024]^T
    sgemm_nt_body(g_attn, w_proj, out, BATCH * SEQ, DIM, DIM);
}

// ---------------------------------------------------------------------------
// Flash attention (fp32), per block: one (b, h, 64-query tile).
// KV tiles of 32. 256 threads: thread (tr=tid/16, tc=tid%16)
//   S fragment: rows 4tr..4tr+3, cols {2tc, 2tc+1}
//   O fragment: rows 4tr..4tr+3, dims 4tc..4tc+3
// Row reductions via width-16 shuffles; P staged through warp-local smem.
// ---------------------------------------------------------------------------
__global__ __launch_bounds__(256, 2)
void attn_kernel(float* __restrict__ dummy /*unused*/)
{
    __shared__ float Qs[64][64];     // [q_row][d]
    __shared__ float Ks[32][68];     // [kv_row][d]  (pad 68 keeps 16B alignment)
    __shared__ float Vs[32][64];     // [kv_row][d]
    __shared__ float Ps[64][36];     // [q_row][kv_col] (pad 36 -> 16B aligned rows)

    const int tid = threadIdx.x;
    const int b  = blockIdx.z;
    const int h  = blockIdx.y;
    const int q0 = blockIdx.x * 64;

    const size_t rowstride = 3 * DIM;                  // 3072 floats per (b,l) row
    const float* base = g_qkv + (size_t)b * SEQ * rowstride + (size_t)h * HDIM;

    // ---- load Q tile [64 x 64] ----
    {
        const int r  = tid >> 2;                       // 0..63
        const float* qrow = base + (size_t)(q0 + r) * rowstride;
#pragma unroll
        for (int i = 0; i < 4; i++) {
            int d = ((tid & 3) + 4 * i) * 4;           // coalesced 64B per 4 lanes
            *(float4*)&Qs[r][d] = *(const float4*)(qrow + d);
        }
    }

    const int tr = tid >> 4;    // 0..15
    const int tc = tid & 15;    // 0..15

    float m[4], l[4], acc[4][4];
#pragma unroll
    for (int i = 0; i < 4; i++) {
        m[i] = -1e30f; l[i] = 0.f;
#pragma unroll
        for (int j = 0; j < 4; j++) acc[i][j] = 0.f;
    }

    for (int kt = 0; kt < SEQ; kt += 32) {
        __syncthreads();   // prior tile fully consumed before overwrite
        // ---- load K,V tiles [32 x 64] each ----
#pragma unroll
        for (int i = 0; i < 2; i++) {
            int idx = tid + 256 * i;
            int r = idx >> 4;            // 0..31
            int c = (idx & 15) * 4;      // 0..60
            const float* krow = base + (size_t)(kt + r) * rowstride + DIM;
            const float* vrow = base + (size_t)(kt + r) * rowstride + 2 * DIM;
            *(float4*)&Ks[r][c] = *(const float4*)(krow + c);
            *(float4*)&Vs[r][c] = *(const float4*)(vrow + c);
        }
        __syncthreads();

        // ---- S = Q K^T fragment ----
        float s0[4], s1[4];
#pragma unroll
        for (int i = 0; i < 4; i++) { s0[i] = 0.f; s1[i] = 0.f; }
#pragma unroll
        for (int d = 0; d < 64; d += 4) {
            float4 k0 = *(const float4*)&Ks[2 * tc    ][d];
            float4 k1 = *(const float4*)&Ks[2 * tc + 1][d];
#pragma unroll
            for (int i = 0; i < 4; i++) {
                float4 q = *(const float4*)&Qs[4 * tr + i][d];
                s0[i] += q.x * k0.x + q.y * k0.y + q.z * k0.z + q.w * k0.w;
                s1[i] += q.x * k1.x + q.y * k1.y + q.z * k1.z + q.w * k1.w;
            }
        }

        // ---- online softmax (rows shared by the 16 lanes with same tr) ----
#pragma unroll
        for (int i = 0; i < 4; i++) {
            float a = s0[i] * SM_SCALE;
            float c2 = s1[i] * SM_SCALE;
            float rmax = fmaxf(a, c2);
#pragma unroll
            for (int o = 8; o > 0; o >>= 1)
                rmax = fmaxf(rmax, __shfl_xor_sync(0xffffffffu, rmax, o));
            float mnew = fmaxf(m[i], rmax);
            float corr = __expf(m[i] - mnew);
            float p0 = __expf(a - mnew);
            float p1 = __expf(c2 - mnew);
            float rs = p0 + p1;
#pragma unroll
            for (int o = 8; o > 0; o >>= 1)
                rs += __shfl_xor_sync(0xffffffffu, rs, o);
            m[i] = mnew;
            l[i] = l[i] * corr + rs;
#pragma unroll
            for (int j = 0; j < 4; j++) acc[i][j] *= corr;
            Ps[4 * tr + i][2 * tc    ] = p0;
            Ps[4 * tr + i][2 * tc + 1] = p1;
        }
        __syncwarp();   // P rows are produced & consumed within the same warp

        // ---- O += P V ----
#pragma unroll
        for (int c = 0; c < 32; c++) {
            float4 v = *(const float4*)&Vs[c][4 * tc];
#pragma unroll
            for (int i = 0; i < 4; i++) {
                float p = Ps[4 * tr + i][c];
                acc[i][0] += p * v.x;
                acc[i][1] += p * v.y;
                acc[i][2] += p * v.z;
                acc[i][3] += p * v.w;
            }
        }
    }

    // ---- epilogue: normalize + write [b, l, h*64 + d] ----
#pragma unroll
    for (int i = 0; i < 4; i++) {
        float inv = 1.f / l[i];
        float4 o = make_float4(acc[i][0] * inv, acc[i][1] * inv,
                               acc[i][2] * inv, acc[i][3] * inv);
        float* orow = g_attn + (size_t)(b * SEQ + q0 + 4 * tr + i) * DIM
                      + h * HDIM + 4 * tc;
        *(float4*)orow = o;
    }
}

// ---------------------------------------------------------------------------
// Launch
// ---------------------------------------------------------------------------
extern "C" void kernel_launch(void* const* d_in, const int* in_sizes, int n_in,
                              void* d_out, int out_size)
{
    const float* x      = (const float*)d_in[0];   // [2, 2048, 1024]
    const float* w_qkv  = (const float*)d_in[1];   // [3072, 1024]
    const float* w_proj = (const float*)d_in[2];   // [1024, 1024]
    float* out = (float*)d_out;                    // [2, 2048, 1024]

    (void)in_sizes; (void)n_in; (void)out_size;

    // 1) QKV projection: [4096,3072] = [4096,1024] @ [3072,1024]^T
    {
        dim3 grid(3 * DIM / 128, BATCH * SEQ / 128);   // 24 x 32
        gemm_qkv<<<grid, 256>>>(x, w_qkv);
    }
    // 2) Attention: per (q-tile, head, batch)
    {
        dim3 grid(SEQ / 64, NHEADS, BATCH);            // 32 x 16 x 2
        attn_kernel<<<grid, 256>>>(nullptr);
    }
    // 3) Output projection: [4096,1024] = [4096,1024] @ [1024,1024]^T
    {
        dim3 grid(DIM / 128, BATCH * SEQ / 128);       // 8 x 32
        gemm_proj<<<grid, 256>>>(w_proj, out);
    }
}

// round 3
// speedup vs baseline: 3.0351x; 3.0351x over previous
#include <cuda_runtime.h>
#include <cuda_bf16.h>
#include <cstdint>

#define BATCH 2
#define SEQ 2048
#define DIM 1024
#define NHEADS 16
#define HDIM 64
#define SM_SCALE 0.125f
#define MROWS 4096           // B*L
#define KP 3072              // packed K' = 3*DIM
#define NCH 48               // KP / 64

// ---------------------------------------------------------------------------
// Scratch (device globals: allocation-free)
// ---------------------------------------------------------------------------
__device__ __align__(16) float g_qkv[(size_t)MROWS * 3 * DIM];   // 48 MB
__device__ __align__(16) float g_attn[(size_t)MROWS * DIM];      // 16 MB
__device__ __align__(16) __nv_bfloat16 g_xp [(size_t)MROWS * KP];    // x packed  (hi|lo|hi)
__device__ __align__(16) __nv_bfloat16 g_wqp[(size_t)3 * DIM * KP];  // w_qkv     (hi|hi|lo)
__device__ __align__(16) __nv_bfloat16 g_wpp[(size_t)DIM * KP];      // w_proj    (hi|hi|lo)
__device__ __align__(16) __nv_bfloat16 g_aop[(size_t)MROWS * KP];    // attn out  (hi|lo|hi)

// ---------------------------------------------------------------------------
// Base-ISA helpers (no 'a' features: mma.sync / ldmatrix / cp.async only)
// ---------------------------------------------------------------------------
__device__ __forceinline__ uint32_t smem_u32(const void* p) {
    uint32_t a;
    asm("{ .reg .u64 t; cvta.to.shared.u64 t, %1; cvt.u32.u64 %0, t; }"
        : "=r"(a) : "l"(p));
    return a;
}

__device__ __forceinline__ void ldsm4(uint32_t* r, uint32_t a) {
    asm volatile("ldmatrix.sync.aligned.m8n8.x4.shared.b16 {%0,%1,%2,%3}, [%4];"
        : "=r"(r[0]), "=r"(r[1]), "=r"(r[2]), "=r"(r[3]) : "r"(a));
}
__device__ __forceinline__ void ldsm4t(uint32_t* r, uint32_t a) {
    asm volatile("ldmatrix.sync.aligned.m8n8.x4.trans.shared.b16 {%0,%1,%2,%3}, [%4];"
        : "=r"(r[0]), "=r"(r[1]), "=r"(r[2]), "=r"(r[3]) : "r"(a));
}

__device__ __forceinline__ void mma_bf16(float* c, const uint32_t* a, const uint32_t* b) {
    asm volatile(
        "mma.sync.aligned.m16n8k16.row.col.f32.bf16.bf16.f32 "
        "{%0,%1,%2,%3}, {%4,%5,%6,%7}, {%8,%9}, {%0,%1,%2,%3};"
        : "+f"(c[0]), "+f"(c[1]), "+f"(c[2]), "+f"(c[3])
        : "r"(a[0]), "r"(a[1]), "r"(a[2]), "r"(a[3]), "r"(b[0]), "r"(b[1]));
}

#define CPA16(d, s) \
    asm volatile("cp.async.cg.shared.global [%0], [%1], 16;" :: "r"(d), "l"(s))
#define CP_COMMIT() asm volatile("cp.async.commit_group;" ::: "memory")

// pack two floats into bf16x2 (x -> low half, y -> high half)
__device__ __forceinline__ uint32_t pack2bf(float x, float y) {
    __nv_bfloat162 t = __float22bfloat162_rn(make_float2(x, y));
    return *reinterpret_cast<uint32_t*>(&t);
}
// residual (lo) pack given the hi pack
__device__ __forceinline__ uint32_t packresid(uint32_t hp, float x, float y) {
    float hx = __uint_as_float(hp << 16);
    float hy = __uint_as_float(hp & 0xffff0000u);
    return pack2bf(x - hx, y - hy);
}

// ---------------------------------------------------------------------------
// Split + pack: fp32 [rows,1024] -> bf16 [rows,3072]
//   amode=1 (activations): [hi | lo | hi]
//   amode=0 (weights):     [hi | hi | lo]
// dst selector avoids host symbol queries.
// ---------------------------------------------------------------------------
__global__ void split_pack(const float* __restrict__ in, int dst, int amode)
{
    const float* src = in ? in : g_attn;
    __nv_bfloat16* out = (dst == 0) ? g_xp : (dst == 1) ? g_wqp
                       : (dst == 2) ? g_wpp : g_aop;
    size_t idx = (size_t)blockIdx.x * 256 + threadIdx.x;
    size_t m = idx >> 8;
    int k = (int)(idx & 255) * 4;
    float4 v = *(const float4*)(src + m * DIM + k);
    uint32_t h0 = pack2bf(v.x, v.y), h1 = pack2bf(v.z, v.w);
    uint32_t l0 = packresid(h0, v.x, v.y), l1 = packresid(h1, v.z, v.w);
    __nv_bfloat16* o = out + m * KP + k;
    uint2 hi = make_uint2(h0, h1), lo = make_uint2(l0, l1);
    *(uint2*)(o) = hi;
    if (amode) { *(uint2*)(o + DIM) = lo; *(uint2*)(o + 2 * DIM) = hi; }
    else       { *(uint2*)(o + DIM) = hi; *(uint2*)(o + 2 * DIM) = lo; }
}

// ---------------------------------------------------------------------------
// bf16 HMMA GEMM: C[M,N] = A'[M,KP] * B'[N,KP]^T   (fp32 accum/out)
// 128x128 CTA tile, k-chunk 64 (128B rows, XOR swizzle), 3-stage cp.async.
// 8 warps as 4(m) x 2(n): warp tile 32m x 64n.
// ---------------------------------------------------------------------------
#define GSTAGE_BYTES 32768        // A 16K + B 16K
#define GB_OFF 16384
#define GSMEM (3 * GSTAGE_BYTES)  // 96 KB

__global__ __launch_bounds__(256, 2)
void gemm_bf16(int asel /*0:g_xp 1:g_aop*/, int bsel /*0:g_wqp 1:g_wpp*/,
               float* __restrict__ Cout /*null -> g_qkv*/, int N)
{
    const __nv_bfloat16* A = asel ? g_aop : g_xp;
    const __nv_bfloat16* B = bsel ? g_wpp : g_wqp;
    float* C = Cout ? Cout : g_qkv;

    extern __shared__ char sm[];
    const uint32_t sb = smem_u32(sm);
    const int tid = threadIdx.x, lane = tid & 31, wid = tid >> 5;
    const int wm = wid >> 1, wn = wid & 1;
    const int bm = blockIdx.y * 128, bn = blockIdx.x * 128;

    const __nv_bfloat16* Ag = A + (size_t)bm * KP;
    const __nv_bfloat16* Bg = B + (size_t)bn * KP;

    const int ldrow = tid >> 1;        // 0..127
    const int ldc0 = (tid & 1) * 4;    // col16 base (0 or 4)

    auto load_stage = [&](int ch, int s) {
        const size_t ko = (size_t)ch * 64;
        uint32_t base = sb + s * GSTAGE_BYTES;
        const __nv_bfloat16* a = Ag + (size_t)ldrow * KP + ko;
        const __nv_bfloat16* b = Bg + (size_t)ldrow * KP + ko;
        uint32_t rbase = base + ldrow * 128;
#pragma unroll
        for (int i = 0; i < 4; i++) {
            int c16 = ldc0 + i;
            uint32_t sw = rbase + (uint32_t)((c16 ^ (ldrow & 7)) << 4);
            CPA16(sw, a + c16 * 8);
            CPA16(sw + GB_OFF, b + c16 * 8);
        }
        CP_COMMIT();
    };

    load_stage(0, 0);
    load_stage(1, 1);

    float acc[2][8][4];
#pragma unroll
    for (int i = 0; i < 2; i++)
#pragma unroll
        for (int j = 0; j < 8; j++)
#pragma unroll
            for (int q = 0; q < 4; q++) acc[i][j][q] = 0.f;

    const int arow0 = wm * 32 + (lane & 15);
    const int alc = lane >> 4;                     // 0/1
    const int brow0 = wn * 64 + ((lane >> 4) & 1) * 8 + (lane & 7);
    const int bc = (lane >> 3) & 1;

    for (int ch = 0; ch < NCH; ch++) {
        const int s = ch % 3;
        if (ch + 1 < NCH) { asm volatile("cp.async.wait_group 1;" ::: "memory"); }
        else              { asm volatile("cp.async.wait_group 0;" ::: "memory"); }
        __syncthreads();
        const uint32_t Ab = sb + s * GSTAGE_BYTES;
        const uint32_t Bb = Ab + GB_OFF;
#pragma unroll
        for (int kk = 0; kk < 4; kk++) {
            uint32_t a0[4], a1[4];
            {
                int c = kk * 2 + alc;
                int r0 = arow0;
                ldsm4(a0, Ab + r0 * 128 + ((c ^ (r0 & 7)) << 4));
                int r1 = arow0 + 16;
                ldsm4(a1, Ab + r1 * 128 + ((c ^ (r1 & 7)) << 4));
            }
#pragma unroll
            for (int bp = 0; bp < 4; bp++) {
                uint32_t b[4];
                int r = brow0 + bp * 16;
                int c = kk * 2 + bc;
                ldsm4(b, Bb + r * 128 + ((c ^ (r & 7)) << 4));
                mma_bf16(acc[0][2 * bp],     a0, b);
                mma_bf16(acc[0][2 * bp + 1], a0, b + 2);
                mma_bf16(acc[1][2 * bp],     a1, b);
                mma_bf16(acc[1][2 * bp + 1], a1, b + 2);
            }
        }
        if (ch + 2 < NCH) load_stage(ch + 2, (ch + 2) % 3);
    }

    const int g = lane >> 2, t = lane & 3;
#pragma unroll
    for (int mf = 0; mf < 2; mf++) {
        int row = bm + wm * 32 + mf * 16 + g;
#pragma unroll
        for (int nf = 0; nf < 8; nf++) {
            int col = bn + wn * 64 + nf * 8 + t * 2;
            *(float2*)(C + (size_t)row * N + col) =
                make_float2(acc[mf][nf][0], acc[mf][nf][1]);
            *(float2*)(C + (size_t)(row + 8) * N + col) =
                make_float2(acc[mf][nf][2], acc[mf][nf][3]);
        }
    }
}

// ---------------------------------------------------------------------------
// Flash attention on HMMA. Block = 128 thr (4 warps), 64 q-rows; KV tile 64.
// S = (Qhi+Qlo)(Khi+Klo)^T (3 products), fp32 online softmax in accum regs,
// P hi/lo split in registers, O += (Phi+Plo)(Vhi+Vlo) (3 products).
// ---------------------------------------------------------------------------
#define AQH 0
#define AQL 8192
#define AKH 16384
#define AKL 24576
#define AVH 32768
#define AVL 40960

__global__ __launch_bounds__(128, 3)
void attn_tc()
{
    __shared__ __align__(16) char smem[49152];
    const uint32_t sb = smem_u32(smem);
    const int tid = threadIdx.x, lane = tid & 31, wid = tid >> 5;
    const int b = blockIdx.z, h = blockIdx.y, q0 = blockIdx.x * 64;

    const float* base = g_qkv + (size_t)b * SEQ * 3072 + h * 64;

    // ---- load Q (64x64 fp32) -> hi/lo bf16 smem ----
#pragma unroll
    for (int i = 0; i < 8; i++) {
        int cidx = i * 128 + tid;
        int row = cidx >> 4, c8 = cidx & 15;
        float4 v = *(const float4*)(base + (size_t)(q0 + row) * 3072 + c8 * 4);
        uint32_t h0 = pack2bf(v.x, v.y), h1 = pack2bf(v.z, v.w);
        uint32_t l0 = packresid(h0, v.x, v.y), l1 = packresid(h1, v.z, v.w);
        uint32_t off = row * 128 + (((c8 >> 1) ^ (row & 7)) << 4) + (c8 & 1) * 8;
        *(uint2*)(smem + AQH + off) = make_uint2(h0, h1);
        *(uint2*)(smem + AQL + off) = make_uint2(l0, l1);
    }
    __syncthreads();

    // ---- Q fragments resident in registers ----
    uint32_t qh[4][4], ql[4][4];
    {
        int r = wid * 16 + (lane & 15);
        int cl = lane >> 4;
#pragma unroll
        for (int kk = 0; kk < 4; kk++) {
            uint32_t off = r * 128 + (((kk * 2 + cl) ^ (r & 7)) << 4);
            ldsm4(qh[kk], sb + AQH + off);
            ldsm4(ql[kk], sb + AQL + off);
        }
    }

    float o[8][4];
#pragma unroll
    for (int i = 0; i < 8; i++)
#pragma unroll
        for (int j = 0; j < 4; j++) o[i][j] = 0.f;
    float m0 = -1e30f, m1 = -1e30f, l0s = 0.f, l1s = 0.f;

    const int brow0 = ((lane >> 4) & 1) * 8 + (lane & 7);
    const int bc = (lane >> 3) & 1;
    const int vlc = lane >> 4;

    for (int kt = 0; kt < SEQ; kt += 64) {
        __syncthreads();
        // ---- load K,V tiles (64x64 fp32 each) -> hi/lo smem ----
#pragma unroll
        for (int i = 0; i < 8; i++) {
            int cidx = i * 128 + tid;
            int row = cidx >> 4, c8 = cidx & 15;
            const float* rp = base + (size_t)(kt + row) * 3072 + c8 * 4;
            uint32_t off = row * 128 + (((c8 >> 1) ^ (row & 7)) << 4) + (c8 & 1) * 8;
            float4 kv = *(const float4*)(rp + 1024);
            uint32_t kh0 = pack2bf(kv.x, kv.y), kh1 = pack2bf(kv.z, kv.w);
            *(uint2*)(smem + AKH + off) = make_uint2(kh0, kh1);
            *(uint2*)(smem + AKL + off) =
                make_uint2(packresid(kh0, kv.x, kv.y), packresid(kh1, kv.z, kv.w));
            float4 vv = *(const float4*)(rp + 2048);
            uint32_t vh0 = pack2bf(vv.x, vv.y), vh1 = pack2bf(vv.z, vv.w);
            *(uint2*)(smem + AVH + off) = make_uint2(vh0, vh1);
            *(uint2*)(smem + AVL + off) =
                make_uint2(packresid(vh0, vv.x, vv.y), packresid(vh1, vv.z, vv.w));
        }
        __syncthreads();

        // ---- S = Q K^T (16 x 64 per warp) ----
        float s[8][4];
#pragma unroll
        for (int i = 0; i < 8; i++)
#pragma unroll
            for (int j = 0; j < 4; j++) s[i][j] = 0.f;

#pragma unroll
        for (int kk = 0; kk < 4; kk++) {
#pragma unroll
            for (int bp = 0; bp < 4; bp++) {
                uint32_t bh[4], bl[4];
                int r = brow0 + bp * 16;
                int c = kk * 2 + bc;
                uint32_t off = r * 128 + ((c ^ (r & 7)) << 4);
                ldsm4(bh, sb + AKH + off);
                ldsm4(bl, sb + AKL + off);
                mma_bf16(s[2 * bp],     qh[kk], bh);
                mma_bf16(s[2 * bp + 1], qh[kk], bh + 2);
                mma_bf16(s[2 * bp],     qh[kk], bl);
                mma_bf16(s[2 * bp + 1], qh[kk], bl + 2);
                mma_bf16(s[2 * bp],     ql[kk], bh);
                mma_bf16(s[2 * bp + 1], ql[kk], bh + 2);
            }
        }

        // ---- online softmax (rows g and g+8; quad lanes share a row) ----
        float rmax0 = -1e30f, rmax1 = -1e30f;
#pragma unroll
        for (int nf = 0; nf < 8; nf++) {
            s[nf][0] *= SM_SCALE; s[nf][1] *= SM_SCALE;
            s[nf][2] *= SM_SCALE; s[nf][3] *= SM_SCALE;
            rmax0 = fmaxf(rmax0, fmaxf(s[nf][0], s[nf][1]));
            rmax1 = fmaxf(rmax1, fmaxf(s[nf][2], s[nf][3]));
        }
        rmax0 = fmaxf(rmax0, __shfl_xor_sync(0xffffffffu, rmax0, 1));
        rmax0 = fmaxf(rmax0, __shfl_xor_sync(0xffffffffu, rmax0, 2));
        rmax1 = fmaxf(rmax1, __shfl_xor_sync(0xffffffffu, rmax1, 1));
        rmax1 = fmaxf(rmax1, __shfl_xor_sync(0xffffffffu, rmax1, 2));
        float mn0 = fmaxf(m0, rmax0), mn1 = fmaxf(m1, rmax1);
        float corr0 = __expf(m0 - mn0), corr1 = __expf(m1 - mn1);
        float sum0 = 0.f, sum1 = 0.f;
#pragma unroll
        for (int nf = 0; nf < 8; nf++) {
            s[nf][0] = __expf(s[nf][0] - mn0);
            s[nf][1] = __expf(s[nf][1] - mn0);
            s[nf][2] = __expf(s[nf][2] - mn1);
            s[nf][3] = __expf(s[nf][3] - mn1);
            sum0 += s[nf][0] + s[nf][1];
            sum1 += s[nf][2] + s[nf][3];
        }
        sum0 += __shfl_xor_sync(0xffffffffu, sum0, 1);
        sum0 += __shfl_xor_sync(0xffffffffu, sum0, 2);
        sum1 += __shfl_xor_sync(0xffffffffu, sum1, 1);
        sum1 += __shfl_xor_sync(0xffffffffu, sum1, 2);
        l0s = l0s * corr0 + sum0;
        l1s = l1s * corr1 + sum1;
        m0 = mn0; m1 = mn1;
#pragma unroll
        for (int nf = 0; nf < 8; nf++) {
            o[nf][0] *= corr0; o[nf][1] *= corr0;
            o[nf][2] *= corr1; o[nf][3] *= corr1;
        }

        // ---- O += P V ----
#pragma unroll
        for (int kk = 0; kk < 4; kk++) {
            uint32_t ah[4], al[4];
            ah[0] = pack2bf(s[2 * kk][0], s[2 * kk][1]);
            ah[1] = pack2bf(s[2 * kk][2], s[2 * kk][3]);
            ah[2] = pack2bf(s[2 * kk + 1][0], s[2 * kk + 1][1]);
            ah[3] = pack2bf(s[2 * kk + 1][2], s[2 * kk + 1][3]);
            al[0] = packresid(ah[0], s[2 * kk][0], s[2 * kk][1]);
            al[1] = packresid(ah[1], s[2 * kk][2], s[2 * kk][3]);
            al[2] = packresid(ah[2], s[2 * kk + 1][0], s[2 * kk + 1][1]);
            al[3] = packresid(ah[3], s[2 * kk + 1][2], s[2 * kk + 1][3]);
#pragma unroll
            for (int hp = 0; hp < 4; hp++) {
                uint32_t vh[4], vl[4];
                int r = kk * 16 + ((lane >> 3) & 1) * 8 + (lane & 7);
                int c = hp * 2 + vlc;
                uint32_t off = r * 128 + ((c ^ (r & 7)) << 4);
                ldsm4t(vh, sb + AVH + off);
                ldsm4t(vl, sb + AVL + off);
                mma_bf16(o[2 * hp],     ah, vh);
                mma_bf16(o[2 * hp + 1], ah, vh + 2);
                mma_bf16(o[2 * hp],     ah, vl);
                mma_bf16(o[2 * hp + 1], ah, vl + 2);
                mma_bf16(o[2 * hp],     al, vh);
                mma_bf16(o[2 * hp + 1], al, vh + 2);
            }
        }
    }

    // ---- epilogue ----
    const int g = lane >> 2, t = lane & 3;
    float inv0 = 1.f / l0s, inv1 = 1.f / l1s;
    int row = b * SEQ + q0 + wid * 16 + g;
#pragma unroll
    for (int nf = 0; nf < 8; nf++) {
        int col = h * 64 + nf * 8 + t * 2;
        *(float2*)(g_attn + (size_t)row * DIM + col) =
            make_float2(o[nf][0] * inv0, o[nf][1] * inv0);
        *(float2*)(g_attn + (size_t)(row + 8) * DIM + col) =
            make_float2(o[nf][2] * inv1, o[nf][3] * inv1);
    }
}

// ---------------------------------------------------------------------------
// Launch
// ---------------------------------------------------------------------------
extern "C" void kernel_launch(void* const* d_in, const int* in_sizes, int n_in,
                              void* d_out, int out_size)
{
    const float* x      = (const float*)d_in[0];
    const float* w_qkv  = (const float*)d_in[1];
    const float* w_proj = (const float*)d_in[2];
    float* out = (float*)d_out;
    (void)in_sizes; (void)n_in; (void)out_size;

    cudaFuncSetAttribute(gemm_bf16, cudaFuncAttributeMaxDynamicSharedMemorySize, GSMEM);

    // splits/packs
    split_pack<<<MROWS, 256>>>(x, 0, 1);
    split_pack<<<3 * DIM, 256>>>(w_qkv, 1, 0);
    split_pack<<<DIM, 256>>>(w_proj, 2, 0);

    // QKV projection: [4096,3072] over K'=3072
    gemm_bf16<<<dim3(3 * DIM / 128, MROWS / 128), 256, GSMEM>>>(0, 0, nullptr, 3 * DIM);

    // attention
    attn_tc<<<dim3(SEQ / 64, NHEADS, BATCH), 128>>>();

    // output projection
    split_pack<<<MROWS, 256>>>(nullptr, 3, 1);
    gemm_bf16<<<dim3(DIM / 128, MROWS / 128), 256, GSMEM>>>(1, 1, out, DIM);
}